// round 14
// baseline (speedup 1.0000x reference)
#include <cuda_runtime.h>
#include <cuda_fp16.h>
#include <cstdint>

// ---------------- problem constants ----------------
#define M_IMG   131072      // 8 * 128 * 128 image pixels
#define NB      2888        // 8 * 19 * 19 windows
#define QHW     19
#define NHEADS  16

// ---------------- scratch (static device allocations) ----------------
__device__ __align__(16) __half g_xh[67108864];    // x fp16 (image layout)
__device__ __align__(16) __half g_wi_h[786432];    // W_in  fp16
__device__ __align__(16) __half g_wo_h[262144];    // W_out fp16
__device__ __align__(16) __half g_qkvh[201326592]; // qkv fp16 (image layout)
__device__ __align__(16) __half g_atth[67108864];  // attn out fp16 (image layout)
__device__ __align__(16) __half g_hrow[1536];      // halo qkv row = fp16(bias)
__device__ __align__(16) float  g_rpeT[2704];      // rpe transposed [16][169]

__device__ __forceinline__ void ldsm4(unsigned& r0, unsigned& r1, unsigned& r2, unsigned& r3,
                                      uint32_t addr) {
    asm volatile("ldmatrix.sync.aligned.m8n8.x4.shared.b16 {%0,%1,%2,%3}, [%4];"
                 : "=r"(r0), "=r"(r1), "=r"(r2), "=r"(r3) : "r"(addr));
}

__device__ __forceinline__ void mma_f16(float& d0, float& d1, float& d2, float& d3,
                                        unsigned a0, unsigned a1, unsigned a2, unsigned a3,
                                        unsigned b0, unsigned b1) {
    asm volatile("mma.sync.aligned.m16n8k16.row.col.f32.f16.f16.f32 "
                 "{%0,%1,%2,%3}, {%4,%5,%6,%7}, {%8,%9}, {%0,%1,%2,%3};"
                 : "+f"(d0), "+f"(d1), "+f"(d2), "+f"(d3)
                 : "r"(a0), "r"(a1), "r"(a2), "r"(a3), "r"(b0), "r"(b1));
}

__device__ __forceinline__ void cp16(uint32_t dst, const void* src) {
    asm volatile("cp.async.cg.shared.global [%0], [%1], 16;" :: "r"(dst), "l"(src));
}
__device__ __forceinline__ void cp_commit() { asm volatile("cp.async.commit_group;"); }
template <int N>
__device__ __forceinline__ void cp_waitg() {
    asm volatile("cp.async.wait_group %0;" :: "n"(N) : "memory");
}

// GEMM smem: rows of 64 halfs (128B data) padded to 144B; A=128 rows, B=128 rows
#define R2B    144
#define ATILEB (128 * R2B)               // 18432
#define STAGEB (2 * ATILEB)              // 36864
#define GSMEMB (2 * STAGEB)              // 73728 (2 stages; 2 CTAs/SM)

// one stage (BK=64 = 4 k16-steps), warp tile 64x64
__device__ __forceinline__ void compute_stage64h(uint32_t aB, uint32_t bB,
                                                 float acc[4][8][4]) {
    #pragma unroll
    for (int kk = 0; kk < 4; kk++) {
        unsigned af[4][4];
        #pragma unroll
        for (int mi = 0; mi < 4; mi++)
            ldsm4(af[mi][0], af[mi][1], af[mi][2], af[mi][3],
                  aB + (unsigned)(mi * 16 * R2B + kk * 32));
        unsigned bf[4][4];
        #pragma unroll
        for (int p = 0; p < 4; p++)
            ldsm4(bf[p][0], bf[p][1], bf[p][2], bf[p][3],
                  bB + (unsigned)(p * 16 * R2B + kk * 32));
        #pragma unroll
        for (int mi = 0; mi < 4; mi++)
            #pragma unroll
            for (int p = 0; p < 4; p++) {
                mma_f16(acc[mi][2*p][0], acc[mi][2*p][1], acc[mi][2*p][2], acc[mi][2*p][3],
                        af[mi][0], af[mi][1], af[mi][2], af[mi][3],
                        bf[p][0], bf[p][2]);
                mma_f16(acc[mi][2*p+1][0], acc[mi][2*p+1][1], acc[mi][2*p+1][2], acc[mi][2*p+1][3],
                        af[mi][0], af[mi][1], af[mi][2], af[mi][3],
                        bf[p][1], bf[p][3]);
            }
    }
}

// ---------------- fp16 preconvert (+ rpe transpose) ----------------
#define XN4  16777216
#define WIN4 196608
#define WON4 65536
__global__ void cvt_all(const float* __restrict__ x, const float* __restrict__ wi,
                        const float* __restrict__ wo, const float* __restrict__ bi,
                        const float* __restrict__ rpe) {
    if (blockIdx.x == 0) {
        for (int i = threadIdx.x; i < 1536; i += 256)
            g_hrow[i] = __float2half_rn(bi[i]);
    }
    if (blockIdx.x == 1) {
        for (int i = threadIdx.x; i < 2704; i += 256) {
            const int h = i / 169, e = i - h * 169;
            g_rpeT[i] = rpe[e * NHEADS + h];
        }
    }
    const int stride = gridDim.x * blockDim.x;
    for (int i = blockIdx.x * blockDim.x + threadIdx.x;
         i < XN4 + WIN4 + WON4; i += stride) {
        const float4* src;
        uint2* dst;
        if (i < XN4) {
            src = reinterpret_cast<const float4*>(x) + i;
            dst = reinterpret_cast<uint2*>(g_xh) + i;
        } else if (i < XN4 + WIN4) {
            src = reinterpret_cast<const float4*>(wi) + (i - XN4);
            dst = reinterpret_cast<uint2*>(g_wi_h) + (i - XN4);
        } else {
            src = reinterpret_cast<const float4*>(wo) + (i - XN4 - WIN4);
            dst = reinterpret_cast<uint2*>(g_wo_h) + (i - XN4 - WIN4);
        }
        float4 v = *src;
        __half2 h0 = __floats2half2_rn(v.x, v.y);
        __half2 h1 = __floats2half2_rn(v.z, v.w);
        uint2 u;
        u.x = reinterpret_cast<unsigned&>(h0);
        u.y = reinterpret_cast<unsigned&>(h1);
        *dst = u;
    }
}

// =====================================================================
// GEMM 1 (fp16, 128 thr, warp tile 64x64, BK=64): qkv = x_h @ Win^T + bin
// =====================================================================
__global__ __launch_bounds__(128, 2) void qkv_gemm_mma(const float* __restrict__ bias)
{
    extern __shared__ char smem[];
    const int tid = threadIdx.x, lane = tid & 31, wid = tid >> 5;
    const int wm = wid >> 1, wn = wid & 1;
    const int m0 = blockIdx.y * 128, n0 = blockIdx.x * 128;

    const int lrow = tid >> 3;
    const int seg  = tid & 7;

    const __half* asrc = g_xh   + (size_t)(m0 + lrow) * 512 + seg * 8;
    const __half* bsrc = g_wi_h + (size_t)(n0 + lrow) * 512 + seg * 8;

    const uint32_t s0 = (uint32_t)__cvta_generic_to_shared(smem);
    const uint32_t adst = s0 + lrow * R2B + seg * 16;
    const uint32_t bdst = adst + ATILEB;

    const uint32_t foff = (uint32_t)((lane & 15) * R2B + (lane >> 4) * 16);
    const uint32_t aoff = wm * 64 * R2B + foff;
    const uint32_t boff = wn * 64 * R2B + foff;

    float acc[4][8][4];
    #pragma unroll
    for (int i = 0; i < 4; i++)
        #pragma unroll
        for (int j = 0; j < 8; j++)
            #pragma unroll
            for (int q = 0; q < 4; q++) acc[i][j][q] = 0.f;

    auto load = [&](int it, int buf) {
        const int k0 = it * 64;
        const uint32_t off = buf * STAGEB;
        #pragma unroll
        for (int i = 0; i < 8; i++)
            cp16(adst + off + i * 16 * R2B, asrc + k0 + (size_t)i * 16 * 512);
        #pragma unroll
        for (int i = 0; i < 8; i++)
            cp16(bdst + off + i * 16 * R2B, bsrc + k0 + (size_t)i * 16 * 512);
        cp_commit();
    };

    load(0, 0);

    const uint32_t abase[2] = { s0 + aoff, s0 + STAGEB + aoff };
    const uint32_t bbase[2] = { s0 + ATILEB + boff, s0 + STAGEB + ATILEB + boff };

    #pragma unroll 1
    for (int it = 0; it < 8; ++it) {
        cp_waitg<0>();
        __syncthreads();
        if (it < 7) load(it + 1, (it + 1) & 1);
        compute_stage64h(abase[it & 1], bbase[it & 1], acc);
    }

    #pragma unroll
    for (int i = 0; i < 4; i++) {
        const int r0 = m0 + wm * 64 + i * 16 + (lane >> 2);
        #pragma unroll
        for (int j = 0; j < 8; j++) {
            const int col = n0 + wn * 64 + j * 8 + (lane & 3) * 2;
            const float b0 = bias[col], b1 = bias[col + 1];
            __half2 o0 = __floats2half2_rn(acc[i][j][0] + b0, acc[i][j][1] + b1);
            __half2 o1 = __floats2half2_rn(acc[i][j][2] + b0, acc[i][j][3] + b1);
            *reinterpret_cast<__half2*>(&g_qkvh[(size_t)r0 * 1536 + col]) = o0;
            *reinterpret_cast<__half2*>(&g_qkvh[(size_t)(r0 + 8) * 1536 + col]) = o1;
        }
    }
}

// =====================================================================
// Attention (fp16 mma, register softmax): block = (window, head), 64 thr.
//   Warp wh owns score rows [32wh, 32wh+32) x all 64 cols. Softmax on
//   C-fragments in registers (quad shfl reductions); P repacked directly
//   into A-fragments for P@V. One barrier total.
// =====================================================================
__global__ __launch_bounds__(64) void attn_mma()
{
    __shared__ __align__(16) __half qs[64 * 40];
    __shared__ __align__(16) __half ks[64 * 40];
    __shared__ __align__(16) __half vT[32 * 72];
    __shared__ float bsm[169];
    __shared__ int   s_pix[49];

    const int tid  = threadIdx.x;
    const int wh   = tid >> 5;
    const int lane = tid & 31;

    const int wb   = blockIdx.x;
    const int head = blockIdx.y;
    const float scale = 0.17677669529663687f;   // 32^-0.5

    if (tid < 49) {
        const int b  = wb / (QHW * QHW);
        const int rm = wb - b * (QHW * QHW);
        const int qi = rm / QHW, qj = rm - (rm / QHW) * QHW;
        const int r = qi * 7 + tid / 7 - 2;
        const int c = qj * 7 + (tid % 7) - 2;
        s_pix[tid] = ((unsigned)r < 128u && (unsigned)c < 128u)
                   ? (b * 16384 + r * 128 + c) : -1;
    }
    __syncthreads();

    // zero vT (token cols 49-63 must be exactly 0 for P@V)
    #pragma unroll 1
    for (int i = tid; i < 32 * 72 / 2; i += 64)
        reinterpret_cast<unsigned*>(vT)[i] = 0u;

    // gather q/k rows + transpose v
    #pragma unroll 1
    for (int i = tid; i < 196; i += 64) {
        const int t = i >> 2, d8 = (i & 3) * 8;
        const int pix = s_pix[t];
        const __half* p = ((pix >= 0) ? g_qkvh + (size_t)pix * 1536 : g_hrow)
                        + head * 32 + d8;
        uint4 q4 = *reinterpret_cast<const uint4*>(p);
        uint4 k4 = *reinterpret_cast<const uint4*>(p + 512);
        uint4 v4 = *reinterpret_cast<const uint4*>(p + 1024);
        *reinterpret_cast<uint4*>(&qs[t * 40 + d8]) = q4;
        *reinterpret_cast<uint4*>(&ks[t * 40 + d8]) = k4;
        const __half2* vp = reinterpret_cast<const __half2*>(&v4);
        #pragma unroll
        for (int j = 0; j < 4; j++) {
            __half2 hv = vp[j];
            vT[(d8 + 2 * j) * 72 + t]     = __low2half(hv);
            vT[(d8 + 2 * j + 1) * 72 + t] = __high2half(hv);
        }
    }
    for (int i = tid; i < 169; i += 64) bsm[i] = g_rpeT[head * 169 + i];
    __syncthreads();

    const int g  = lane >> 2;
    const int c2 = (lane & 3) * 2;
    const uint32_t fo40 = (uint32_t)((lane & 15) * 80 + (lane >> 4) * 16);
    const uint32_t fo72 = (uint32_t)((lane & 15) * 144 + (lane >> 4) * 16);

    // ---- QK^T: warp wh computes rows [wh*32, wh*32+32) x cols [0,64) ----
    float acc[2][8][4];
    #pragma unroll
    for (int i = 0; i < 2; i++)
        #pragma unroll
        for (int j = 0; j < 8; j++)
            #pragma unroll
            for (int q = 0; q < 4; q++) acc[i][j][q] = 0.f;

    {
        const uint32_t qb = (uint32_t)__cvta_generic_to_shared(qs) + wh * 32 * 80 + fo40;
        const uint32_t kb = (uint32_t)__cvta_generic_to_shared(ks) + fo40;

        #pragma unroll
        for (int kk = 0; kk < 2; kk++) {
            unsigned af[2][4];
            #pragma unroll
            for (int mi = 0; mi < 2; mi++)
                ldsm4(af[mi][0], af[mi][1], af[mi][2], af[mi][3],
                      qb + (unsigned)(mi * 16 * 80 + kk * 32));
            unsigned bf[4][4];
            #pragma unroll
            for (int p = 0; p < 4; p++)
                ldsm4(bf[p][0], bf[p][1], bf[p][2], bf[p][3],
                      kb + (unsigned)(p * 16 * 80 + kk * 32));
            #pragma unroll
            for (int mi = 0; mi < 2; mi++)
                #pragma unroll
                for (int p = 0; p < 4; p++) {
                    mma_f16(acc[mi][2*p][0], acc[mi][2*p][1], acc[mi][2*p][2], acc[mi][2*p][3],
                            af[mi][0], af[mi][1], af[mi][2], af[mi][3],
                            bf[p][0], bf[p][2]);
                    mma_f16(acc[mi][2*p+1][0], acc[mi][2*p+1][1], acc[mi][2*p+1][2], acc[mi][2*p+1][3],
                            af[mi][0], af[mi][1], af[mi][2], af[mi][3],
                            bf[p][1], bf[p][3]);
                }
        }
    }

    // ---- register softmax on fragments ----
    // per-column bias offsets (same for all row instances of this thread)
    int cOff[16];   // mr*13 + mc for column m2 (valid cols only)
    #pragma unroll
    for (int nj = 0; nj < 8; nj++)
        #pragma unroll
        for (int j = 0; j < 2; j++) {
            const int m2 = nj * 8 + c2 + j;
            const int mr = m2 / 7, mc = m2 - mr * 7;
            cOff[nj * 2 + j] = mr * 13 + mc;
        }

    #pragma unroll
    for (int mi = 0; mi < 2; mi++) {
        #pragma unroll
        for (int h2 = 0; h2 < 2; h2++) {
            const int row = wh * 32 + mi * 16 + h2 * 8 + g;
            const int l = (row < 49) ? row : 48;
            const int lr = l / 7, lc = l - lr * 7;
            const int bbase = (lr + 6) * 13 + (lc + 6);
            float mx = -1e30f;
            #pragma unroll
            for (int nj = 0; nj < 8; nj++)
                #pragma unroll
                for (int j = 0; j < 2; j++) {
                    const int m2 = nj * 8 + c2 + j;
                    float v = (m2 < 49)
                            ? acc[mi][nj][h2 * 2 + j] * scale + bsm[bbase - cOff[nj * 2 + j]]
                            : -1e30f;
                    acc[mi][nj][h2 * 2 + j] = v;
                    mx = fmaxf(mx, v);
                }
            mx = fmaxf(mx, __shfl_xor_sync(0xFFFFFFFFu, mx, 1));
            mx = fmaxf(mx, __shfl_xor_sync(0xFFFFFFFFu, mx, 2));
            float sum = 0.f;
            #pragma unroll
            for (int nj = 0; nj < 8; nj++)
                #pragma unroll
                for (int j = 0; j < 2; j++) {
                    const float e = __expf(acc[mi][nj][h2 * 2 + j] - mx);
                    acc[mi][nj][h2 * 2 + j] = e;
                    sum += e;
                }
            sum += __shfl_xor_sync(0xFFFFFFFFu, sum, 1);
            sum += __shfl_xor_sync(0xFFFFFFFFu, sum, 2);
            const float inv = 1.f / sum;
            #pragma unroll
            for (int nj = 0; nj < 8; nj++)
                #pragma unroll
                for (int j = 0; j < 2; j++)
                    acc[mi][nj][h2 * 2 + j] *= inv;
        }
    }

    // ---- pack P into A-fragments (C m16n8 pairs -> A m16k16) ----
    unsigned pf[2][4][4];
    #pragma unroll
    for (int mi = 0; mi < 2; mi++)
        #pragma unroll
        for (int kk = 0; kk < 4; kk++) {
            __half2 t0 = __floats2half2_rn(acc[mi][2*kk][0],   acc[mi][2*kk][1]);
            __half2 t1 = __floats2half2_rn(acc[mi][2*kk][2],   acc[mi][2*kk][3]);
            __half2 t2 = __floats2half2_rn(acc[mi][2*kk+1][0], acc[mi][2*kk+1][1]);
            __half2 t3 = __floats2half2_rn(acc[mi][2*kk+1][2], acc[mi][2*kk+1][3]);
            pf[mi][kk][0] = reinterpret_cast<unsigned&>(t0);
            pf[mi][kk][1] = reinterpret_cast<unsigned&>(t1);
            pf[mi][kk][2] = reinterpret_cast<unsigned&>(t2);
            pf[mi][kk][3] = reinterpret_cast<unsigned&>(t3);
        }

    // ---- P @ V: warp wh computes its 32 rows x all 32 dims ----
    float o[2][4][4];
    #pragma unroll
    for (int i = 0; i < 2; i++)
        #pragma unroll
        for (int j = 0; j < 4; j++)
            #pragma unroll
            for (int q = 0; q < 4; q++) o[i][j][q] = 0.f;

    {
        const uint32_t vb = (uint32_t)__cvta_generic_to_shared(vT) + fo72;
        #pragma unroll
        for (int kk = 0; kk < 4; kk++) {
            unsigned bf[2][4];
            #pragma unroll
            for (int p = 0; p < 2; p++)
                ldsm4(bf[p][0], bf[p][1], bf[p][2], bf[p][3],
                      vb + (unsigned)(p * 16 * 144 + kk * 32));
            #pragma unroll
            for (int mi = 0; mi < 2; mi++)
                #pragma unroll
                for (int p = 0; p < 2; p++) {
                    mma_f16(o[mi][2*p][0], o[mi][2*p][1], o[mi][2*p][2], o[mi][2*p][3],
                            pf[mi][kk][0], pf[mi][kk][1], pf[mi][kk][2], pf[mi][kk][3],
                            bf[p][0], bf[p][2]);
                    mma_f16(o[mi][2*p+1][0], o[mi][2*p+1][1], o[mi][2*p+1][2], o[mi][2*p+1][3],
                            pf[mi][kk][0], pf[mi][kk][1], pf[mi][kk][2], pf[mi][kk][3],
                            bf[p][1], bf[p][3]);
                }
        }
    }

    // ---- epilogue: scatter rows < 49 ----
    #pragma unroll
    for (int mi = 0; mi < 2; mi++) {
        const int r0 = wh * 32 + mi * 16 + g;
        const int pix0 = (r0 < 49) ? s_pix[r0] : -1;
        const int pix1 = (r0 + 8 < 49) ? s_pix[r0 + 8] : -1;
        #pragma unroll
        for (int nj = 0; nj < 4; nj++) {
            const int col = head * 32 + nj * 8 + c2;
            if (pix0 >= 0) {
                __half2 u = __floats2half2_rn(o[mi][nj][0], o[mi][nj][1]);
                *reinterpret_cast<__half2*>(&g_atth[(size_t)pix0 * 512 + col]) = u;
            }
            if (pix1 >= 0) {
                __half2 u = __floats2half2_rn(o[mi][nj][2], o[mi][nj][3]);
                *reinterpret_cast<__half2*>(&g_atth[(size_t)pix1 * 512 + col]) = u;
            }
        }
    }
}

// =====================================================================
// GEMM 2 (fp16, 128 thr, warp tile 64x64, BK=64): out = att_h @ Wout^T + bout
// =====================================================================
__global__ __launch_bounds__(128, 2) void out_gemm_mma(
    const float* __restrict__ bias, float* __restrict__ out)
{
    extern __shared__ char smem[];
    const int tid = threadIdx.x, lane = tid & 31, wid = tid >> 5;
    const int wm = wid >> 1, wn = wid & 1;
    const int m0 = blockIdx.y * 128, n0 = blockIdx.x * 128;

    const int lrow = tid >> 3;
    const int seg  = tid & 7;

    const __half* asrc = g_atth + (size_t)(m0 + lrow) * 512 + seg * 8;
    const __half* bsrc = g_wo_h + (size_t)(n0 + lrow) * 512 + seg * 8;

    const uint32_t s0 = (uint32_t)__cvta_generic_to_shared(smem);
    const uint32_t adst = s0 + lrow * R2B + seg * 16;
    const uint32_t bdst = adst + ATILEB;

    const uint32_t foff = (uint32_t)((lane & 15) * R2B + (lane >> 4) * 16);
    const uint32_t aoff = wm * 64 * R2B + foff;
    const uint32_t boff = wn * 64 * R2B + foff;

    float acc[4][8][4];
    #pragma unroll
    for (int i = 0; i < 4; i++)
        #pragma unroll
        for (int j = 0; j < 8; j++)
            #pragma unroll
            for (int q = 0; q < 4; q++) acc[i][j][q] = 0.f;

    auto load = [&](int it, int buf) {
        const int k0 = it * 64;
        const uint32_t off = buf * STAGEB;
        #pragma unroll
        for (int i = 0; i < 8; i++)
            cp16(adst + off + i * 16 * R2B, asrc + k0 + (size_t)i * 16 * 512);
        #pragma unroll
        for (int i = 0; i < 8; i++)
            cp16(bdst + off + i * 16 * R2B, bsrc + k0 + (size_t)i * 16 * 512);
        cp_commit();
    };

    load(0, 0);

    const uint32_t abase[2] = { s0 + aoff, s0 + STAGEB + aoff };
    const uint32_t bbase[2] = { s0 + ATILEB + boff, s0 + STAGEB + ATILEB + boff };

    #pragma unroll 1
    for (int it = 0; it < 8; ++it) {
        cp_waitg<0>();
        __syncthreads();
        if (it < 7) load(it + 1, (it + 1) & 1);
        compute_stage64h(abase[it & 1], bbase[it & 1], acc);
    }

    #pragma unroll
    for (int i = 0; i < 4; i++) {
        const int r0 = m0 + wm * 64 + i * 16 + (lane >> 2);
        #pragma unroll
        for (int j = 0; j < 8; j++) {
            const int col = n0 + wn * 64 + j * 8 + (lane & 3) * 2;
            const float b0 = bias[col], b1 = bias[col + 1];
            float2 o0 = make_float2(acc[i][j][0] + b0, acc[i][j][1] + b1);
            float2 o1 = make_float2(acc[i][j][2] + b0, acc[i][j][3] + b1);
            *reinterpret_cast<float2*>(&out[(size_t)r0 * 512 + col]) = o0;
            *reinterpret_cast<float2*>(&out[(size_t)(r0 + 8) * 512 + col]) = o1;
        }
    }
}

// =====================================================================
extern "C" void kernel_launch(void* const* d_in, const int* in_sizes, int n_in,
                              void* d_out, int out_size)
{
    const float* x   = (const float*)d_in[0];
    const float* wi  = (const float*)d_in[1];
    const float* bi  = (const float*)d_in[2];
    const float* wo  = (const float*)d_in[3];
    const float* bo  = (const float*)d_in[4];
    const float* rpe = (const float*)d_in[5];
    float* out = (float*)d_out;

    static bool attr_done = false;
    if (!attr_done) {
        cudaFuncSetAttribute(qkv_gemm_mma,
            cudaFuncAttributeMaxDynamicSharedMemorySize, GSMEMB);
        cudaFuncSetAttribute(out_gemm_mma,
            cudaFuncAttributeMaxDynamicSharedMemorySize, GSMEMB);
        attr_done = true;
    }

    const int mtiles = M_IMG / 128;   // 1024

    cvt_all<<<4096, 256>>>(x, wi, wo, bi, rpe);
    qkv_gemm_mma<<<dim3(1536 / 128, mtiles), 128, GSMEMB>>>(bi);
    attn_mma<<<dim3(NB, NHEADS), 64>>>();
    out_gemm_mma<<<dim3(512 / 128, mtiles), 128, GSMEMB>>>(bo, out);
}

// round 16
// speedup vs baseline: 1.4796x; 1.4796x over previous
#include <cuda_runtime.h>
#include <cuda_fp16.h>
#include <cstdint>

// ---------------- problem constants ----------------
#define M_IMG   131072      // 8 * 128 * 128 image pixels
#define NB      2888        // 8 * 19 * 19 windows
#define QHW     19
#define NHEADS  16

// ---------------- scratch (static device allocations) ----------------
__device__ __align__(16) __half g_xh[67108864];    // x fp16 (image layout)
__device__ __align__(16) __half g_wi_h[786432];    // W_in  fp16
__device__ __align__(16) __half g_wo_h[262144];    // W_out fp16
__device__ __align__(16) __half g_qkvh[201326592]; // qkv fp16 (image layout)
__device__ __align__(16) __half g_atth[67108864];  // attn out fp16 (image layout)
__device__ __align__(16) __half g_hrow[1536];      // halo qkv row = fp16(bias)
__device__ __align__(16) float  g_rpeT[2704];      // rpe transposed [16][169]

__device__ __forceinline__ void ldsm4(unsigned& r0, unsigned& r1, unsigned& r2, unsigned& r3,
                                      uint32_t addr) {
    asm volatile("ldmatrix.sync.aligned.m8n8.x4.shared.b16 {%0,%1,%2,%3}, [%4];"
                 : "=r"(r0), "=r"(r1), "=r"(r2), "=r"(r3) : "r"(addr));
}

__device__ __forceinline__ void mma_f16(float& d0, float& d1, float& d2, float& d3,
                                        unsigned a0, unsigned a1, unsigned a2, unsigned a3,
                                        unsigned b0, unsigned b1) {
    asm volatile("mma.sync.aligned.m16n8k16.row.col.f32.f16.f16.f32 "
                 "{%0,%1,%2,%3}, {%4,%5,%6,%7}, {%8,%9}, {%0,%1,%2,%3};"
                 : "+f"(d0), "+f"(d1), "+f"(d2), "+f"(d3)
                 : "r"(a0), "r"(a1), "r"(a2), "r"(a3), "r"(b0), "r"(b1));
}

__device__ __forceinline__ void cp16(uint32_t dst, const void* src) {
    asm volatile("cp.async.cg.shared.global [%0], [%1], 16;" :: "r"(dst), "l"(src));
}
__device__ __forceinline__ void cp_commit() { asm volatile("cp.async.commit_group;"); }
template <int N>
__device__ __forceinline__ void cp_waitg() {
    asm volatile("cp.async.wait_group %0;" :: "n"(N) : "memory");
}

// GEMM smem: XOR-swizzled 128B rows (64 halfs); A=128 rows, B=128 rows, 2 stages
#define ATILEB 16384                     // 128 rows * 128 B
#define STAGEB (2 * ATILEB)              // 32768
#define GSMEMB (2 * STAGEB)              // 65536 (2 stages; 3 CTAs/SM)

// one stage (BK=64 = 4 k16-steps), warp tile 64x64, swizzled fragment loads.
// aRow/bRow = stage base + this thread's ldmatrix row offset (row*128).
// swk[kk] = swizzled chunk byte-offset for k-step kk (same for A and B).
__device__ __forceinline__ void compute_stage64h(uint32_t aRow, uint32_t bRow,
                                                 const uint32_t swk[4],
                                                 float acc[4][8][4]) {
    #pragma unroll
    for (int kk = 0; kk < 4; kk++) {
        unsigned af[4][4];
        #pragma unroll
        for (int mi = 0; mi < 4; mi++)
            ldsm4(af[mi][0], af[mi][1], af[mi][2], af[mi][3],
                  aRow + (unsigned)(mi * 16 * 128) + swk[kk]);
        unsigned bf[4][4];
        #pragma unroll
        for (int p = 0; p < 4; p++)
            ldsm4(bf[p][0], bf[p][1], bf[p][2], bf[p][3],
                  bRow + (unsigned)(p * 16 * 128) + swk[kk]);
        #pragma unroll
        for (int mi = 0; mi < 4; mi++)
            #pragma unroll
            for (int p = 0; p < 4; p++) {
                mma_f16(acc[mi][2*p][0], acc[mi][2*p][1], acc[mi][2*p][2], acc[mi][2*p][3],
                        af[mi][0], af[mi][1], af[mi][2], af[mi][3],
                        bf[p][0], bf[p][2]);
                mma_f16(acc[mi][2*p+1][0], acc[mi][2*p+1][1], acc[mi][2*p+1][2], acc[mi][2*p+1][3],
                        af[mi][0], af[mi][1], af[mi][2], af[mi][3],
                        bf[p][1], bf[p][3]);
            }
    }
}

// ---------------- fp16 preconvert (+ rpe transpose) ----------------
#define XN4  16777216
#define WIN4 196608
#define WON4 65536
__global__ void cvt_all(const float* __restrict__ x, const float* __restrict__ wi,
                        const float* __restrict__ wo, const float* __restrict__ bi,
                        const float* __restrict__ rpe) {
    if (blockIdx.x == 0) {
        for (int i = threadIdx.x; i < 1536; i += 256)
            g_hrow[i] = __float2half_rn(bi[i]);
    }
    if (blockIdx.x == 1) {
        for (int i = threadIdx.x; i < 2704; i += 256) {
            const int h = i / 169, e = i - h * 169;
            g_rpeT[i] = rpe[e * NHEADS + h];
        }
    }
    const int stride = gridDim.x * blockDim.x;
    for (int i = blockIdx.x * blockDim.x + threadIdx.x;
         i < XN4 + WIN4 + WON4; i += stride) {
        const float4* src;
        uint2* dst;
        if (i < XN4) {
            src = reinterpret_cast<const float4*>(x) + i;
            dst = reinterpret_cast<uint2*>(g_xh) + i;
        } else if (i < XN4 + WIN4) {
            src = reinterpret_cast<const float4*>(wi) + (i - XN4);
            dst = reinterpret_cast<uint2*>(g_wi_h) + (i - XN4);
        } else {
            src = reinterpret_cast<const float4*>(wo) + (i - XN4 - WIN4);
            dst = reinterpret_cast<uint2*>(g_wo_h) + (i - XN4 - WIN4);
        }
        float4 v = *src;
        __half2 h0 = __floats2half2_rn(v.x, v.y);
        __half2 h1 = __floats2half2_rn(v.z, v.w);
        uint2 u;
        u.x = reinterpret_cast<unsigned&>(h0);
        u.y = reinterpret_cast<unsigned&>(h1);
        *dst = u;
    }
}

// =====================================================================
// GEMM 1 (fp16, 128 thr, warp tile 64x64, BK=64, swizzled): qkv
// =====================================================================
__global__ __launch_bounds__(128, 3) void qkv_gemm_mma(const float* __restrict__ bias)
{
    extern __shared__ char smem[];
    const int tid = threadIdx.x, lane = tid & 31, wid = tid >> 5;
    const int wm = wid >> 1, wn = wid & 1;
    const int m0 = blockIdx.y * 128, n0 = blockIdx.x * 128;

    const int lrow = tid >> 3;       // 0..15
    const int seg  = tid & 7;        // 16B chunk index

    const __half* asrc = g_xh   + (size_t)(m0 + lrow) * 512 + seg * 8;
    const __half* bsrc = g_wi_h + (size_t)(n0 + lrow) * 512 + seg * 8;

    const uint32_t s0 = (uint32_t)__cvta_generic_to_shared(smem);
    // swizzled store addresses: row lrow, chunk seg ^ (lrow&7)
    const uint32_t adst = s0 + lrow * 128 + ((seg ^ (lrow & 7)) << 4);
    const uint32_t bdst = adst + ATILEB;

    // fragment addressing: row = warpbase + (lane&15); chunk 2kk + (lane>>4), xor (lane&7)
    const uint32_t arow_off = (uint32_t)((wm * 64 + (lane & 15)) * 128);
    const uint32_t brow_off = (uint32_t)((wn * 64 + (lane & 15)) * 128);
    uint32_t swk[4];
    #pragma unroll
    for (int kk = 0; kk < 4; kk++)
        swk[kk] = (uint32_t)((((2 * kk + (lane >> 4)) ^ (lane & 7)) << 4));

    float acc[4][8][4];
    #pragma unroll
    for (int i = 0; i < 4; i++)
        #pragma unroll
        for (int j = 0; j < 8; j++)
            #pragma unroll
            for (int q = 0; q < 4; q++) acc[i][j][q] = 0.f;

    auto load = [&](int it, int buf) {
        const int k0 = it * 64;
        const uint32_t off = buf * STAGEB;
        #pragma unroll
        for (int i = 0; i < 8; i++)
            cp16(adst + off + i * 16 * 128, asrc + k0 + (size_t)i * 16 * 512);
        #pragma unroll
        for (int i = 0; i < 8; i++)
            cp16(bdst + off + i * 16 * 128, bsrc + k0 + (size_t)i * 16 * 512);
        cp_commit();
    };

    load(0, 0);

    #pragma unroll 1
    for (int it = 0; it < 8; ++it) {
        cp_waitg<0>();
        __syncthreads();
        if (it < 7) load(it + 1, (it + 1) & 1);
        const uint32_t st = s0 + (it & 1) * STAGEB;
        compute_stage64h(st + arow_off, st + ATILEB + brow_off, swk, acc);
    }

    #pragma unroll
    for (int i = 0; i < 4; i++) {
        const int r0 = m0 + wm * 64 + i * 16 + (lane >> 2);
        #pragma unroll
        for (int j = 0; j < 8; j++) {
            const int col = n0 + wn * 64 + j * 8 + (lane & 3) * 2;
            const float b0 = bias[col], b1 = bias[col + 1];
            __half2 o0 = __floats2half2_rn(acc[i][j][0] + b0, acc[i][j][1] + b1);
            __half2 o1 = __floats2half2_rn(acc[i][j][2] + b0, acc[i][j][3] + b1);
            *reinterpret_cast<__half2*>(&g_qkvh[(size_t)r0 * 1536 + col]) = o0;
            *reinterpret_cast<__half2*>(&g_qkvh[(size_t)(r0 + 8) * 1536 + col]) = o1;
        }
    }
}

// =====================================================================
// Attention (fp16 mma): one block per (window, head), 64 threads.
//   (R13 version, verbatim — known good)
// =====================================================================
#define AT_QS   0                        // [64][40h] = 5120
#define AT_KS   5120                     // [64][40h] = 5120
#define AT_VT   10240                    // [32][72h] = 4608
#define AT_PH   14848                    // [64][72h] = 9216
#define AT_SP   24064                    // [64][68f] = 17408
#define AT_BSM  41472                    // [169f]    = 676
#define AT_PIX  42148                    // [49i]     = 196
#define AT_SMEMB 42368

__global__ __launch_bounds__(64) void attn_mma()
{
    extern __shared__ char sm[];
    __half* qs  = reinterpret_cast<__half*>(sm + AT_QS);
    __half* ks  = reinterpret_cast<__half*>(sm + AT_KS);
    __half* vT  = reinterpret_cast<__half*>(sm + AT_VT);
    __half* Ph  = reinterpret_cast<__half*>(sm + AT_PH);
    float*  SP  = reinterpret_cast<float*>(sm + AT_SP);
    float*  bsm = reinterpret_cast<float*>(sm + AT_BSM);
    int*  s_pix = reinterpret_cast<int*>(sm + AT_PIX);

    const int tid  = threadIdx.x;
    const int wh   = tid >> 5;
    const int lane = tid & 31;

    const int wb   = blockIdx.x;
    const int head = blockIdx.y;
    const float scale = 0.17677669529663687f;   // 32^-0.5

    if (tid < 49) {
        const int b  = wb / (QHW * QHW);
        const int rm = wb - b * (QHW * QHW);
        const int qi = rm / QHW, qj = rm - (rm / QHW) * QHW;
        const int r = qi * 7 + tid / 7 - 2;
        const int c = qj * 7 + (tid % 7) - 2;
        s_pix[tid] = ((unsigned)r < 128u && (unsigned)c < 128u)
                   ? (b * 16384 + r * 128 + c) : -1;
    }
    __syncthreads();

    #pragma unroll 1
    for (int i = tid; i < 32 * 72 / 2; i += 64)
        reinterpret_cast<unsigned*>(vT)[i] = 0u;

    #pragma unroll 1
    for (int i = tid; i < 196; i += 64) {
        const int t = i >> 2, d8 = (i & 3) * 8;
        const int pix = s_pix[t];
        const __half* p = ((pix >= 0) ? g_qkvh + (size_t)pix * 1536 : g_hrow)
                        + head * 32 + d8;
        uint4 q4 = *reinterpret_cast<const uint4*>(p);
        uint4 k4 = *reinterpret_cast<const uint4*>(p + 512);
        uint4 v4 = *reinterpret_cast<const uint4*>(p + 1024);
        *reinterpret_cast<uint4*>(&qs[t * 40 + d8]) = q4;
        *reinterpret_cast<uint4*>(&ks[t * 40 + d8]) = k4;
        const __half2* vp = reinterpret_cast<const __half2*>(&v4);
        #pragma unroll
        for (int j = 0; j < 4; j++) {
            __half2 hv = vp[j];
            vT[(d8 + 2 * j) * 72 + t]     = __low2half(hv);
            vT[(d8 + 2 * j + 1) * 72 + t] = __high2half(hv);
        }
    }
    for (int i = tid; i < 169; i += 64) bsm[i] = g_rpeT[head * 169 + i];
    __syncthreads();

    const int mrow = lane >> 2;
    const int c2 = (lane & 3) * 2;
    const uint32_t fo40 = (uint32_t)((lane & 15) * 80 + (lane >> 4) * 16);
    const uint32_t fo72 = (uint32_t)((lane & 15) * 144 + (lane >> 4) * 16);

    // ---- QK^T ----
    {
        const uint32_t qb = (uint32_t)__cvta_generic_to_shared(qs) + fo40;
        const uint32_t kb = (uint32_t)__cvta_generic_to_shared(ks) + wh * 32 * 80 + fo40;

        float acc[4][4][4];
        #pragma unroll
        for (int i = 0; i < 4; i++)
            #pragma unroll
            for (int j = 0; j < 4; j++)
                #pragma unroll
                for (int q = 0; q < 4; q++) acc[i][j][q] = 0.f;

        #pragma unroll
        for (int kk = 0; kk < 2; kk++) {
            unsigned af[4][4];
            #pragma unroll
            for (int mi = 0; mi < 4; mi++)
                ldsm4(af[mi][0], af[mi][1], af[mi][2], af[mi][3],
                      qb + (unsigned)(mi * 16 * 80 + kk * 32));
            unsigned bf[2][4];
            #pragma unroll
            for (int p = 0; p < 2; p++)
                ldsm4(bf[p][0], bf[p][1], bf[p][2], bf[p][3],
                      kb + (unsigned)(p * 16 * 80 + kk * 32));
            #pragma unroll
            for (int mi = 0; mi < 4; mi++)
                #pragma unroll
                for (int p = 0; p < 2; p++) {
                    mma_f16(acc[mi][2*p][0], acc[mi][2*p][1], acc[mi][2*p][2], acc[mi][2*p][3],
                            af[mi][0], af[mi][1], af[mi][2], af[mi][3],
                            bf[p][0], bf[p][2]);
                    mma_f16(acc[mi][2*p+1][0], acc[mi][2*p+1][1], acc[mi][2*p+1][2], acc[mi][2*p+1][3],
                            af[mi][0], af[mi][1], af[mi][2], af[mi][3],
                            bf[p][1], bf[p][3]);
                }
        }

        #pragma unroll
        for (int mi = 0; mi < 4; mi++)
            #pragma unroll
            for (int nj = 0; nj < 4; nj++) {
                const int colb = wh * 32 + nj * 8 + c2;
                *reinterpret_cast<float2*>(&SP[(mi * 16 + mrow) * 68 + colb]) =
                    make_float2(acc[mi][nj][0], acc[mi][nj][1]);
                *reinterpret_cast<float2*>(&SP[(mi * 16 + mrow + 8) * 68 + colb]) =
                    make_float2(acc[mi][nj][2], acc[mi][nj][3]);
            }
    }
    __syncthreads();

    // ---- softmax over 49 valid cols; write P as fp16 ----
    if (tid < 49) {
        const int l = tid;
        float* row = SP + l * 68;
        const int lr = l / 7, lc = l - lr * 7;
        float s[49];
        float mx = -1e30f;
        #pragma unroll
        for (int m2 = 0; m2 < 49; m2++) {
            const int mr = m2 / 7, mc = m2 - mr * 7;
            const float v = row[m2] * scale + bsm[(lr - mr + 6) * 13 + (lc - mc + 6)];
            s[m2] = v;
            mx = fmaxf(mx, v);
        }
        float sum = 0.f;
        #pragma unroll
        for (int m2 = 0; m2 < 49; m2++) {
            const float e = __expf(s[m2] - mx);
            s[m2] = e;
            sum += e;
        }
        const float inv = 1.f / sum;
        __half* prow = Ph + l * 72;
        #pragma unroll
        for (int m2 = 0; m2 < 49; m2++) prow[m2] = __float2half_rn(s[m2] * inv);
        #pragma unroll
        for (int m2 = 49; m2 < 64; m2++) prow[m2] = __ushort_as_half(0);
    }
    __syncthreads();

    // ---- P @ V ----
    {
        const uint32_t pb = (uint32_t)__cvta_generic_to_shared(Ph) + fo72;
        const uint32_t vb = (uint32_t)__cvta_generic_to_shared(vT) + wh * 16 * 144 + fo72;

        float o[4][2][4];
        #pragma unroll
        for (int i = 0; i < 4; i++)
            #pragma unroll
            for (int j = 0; j < 2; j++)
                #pragma unroll
                for (int q = 0; q < 4; q++) o[i][j][q] = 0.f;

        #pragma unroll
        for (int kk = 0; kk < 4; kk++) {
            unsigned af[4][4];
            #pragma unroll
            for (int mi = 0; mi < 4; mi++)
                ldsm4(af[mi][0], af[mi][1], af[mi][2], af[mi][3],
                      pb + (unsigned)(mi * 16 * 144 + kk * 32));
            unsigned bf[4];
            ldsm4(bf[0], bf[1], bf[2], bf[3], vb + (unsigned)(kk * 32));
            #pragma unroll
            for (int mi = 0; mi < 4; mi++) {
                mma_f16(o[mi][0][0], o[mi][0][1], o[mi][0][2], o[mi][0][3],
                        af[mi][0], af[mi][1], af[mi][2], af[mi][3], bf[0], bf[2]);
                mma_f16(o[mi][1][0], o[mi][1][1], o[mi][1][2], o[mi][1][3],
                        af[mi][0], af[mi][1], af[mi][2], af[mi][3], bf[1], bf[3]);
            }
        }

        #pragma unroll
        for (int mi = 0; mi < 4; mi++) {
            const int m = mi * 16 + mrow;
            const int pix0 = (m < 49) ? s_pix[m] : -1;
            const int pix1 = (m + 8 < 49) ? s_pix[m + 8] : -1;
            #pragma unroll
            for (int nj = 0; nj < 2; nj++) {
                const int col = head * 32 + wh * 16 + nj * 8 + c2;
                if (pix0 >= 0) {
                    __half2 u = __floats2half2_rn(o[mi][nj][0], o[mi][nj][1]);
                    *reinterpret_cast<__half2*>(&g_atth[(size_t)pix0 * 512 + col]) = u;
                }
                if (pix1 >= 0) {
                    __half2 u = __floats2half2_rn(o[mi][nj][2], o[mi][nj][3]);
                    *reinterpret_cast<__half2*>(&g_atth[(size_t)pix1 * 512 + col]) = u;
                }
            }
        }
    }
}

// =====================================================================
// GEMM 2 (fp16, 128 thr, warp tile 64x64, BK=64, swizzled): out
// =====================================================================
__global__ __launch_bounds__(128, 3) void out_gemm_mma(
    const float* __restrict__ bias, float* __restrict__ out)
{
    extern __shared__ char smem[];
    const int tid = threadIdx.x, lane = tid & 31, wid = tid >> 5;
    const int wm = wid >> 1, wn = wid & 1;
    const int m0 = blockIdx.y * 128, n0 = blockIdx.x * 128;

    const int lrow = tid >> 3;
    const int seg  = tid & 7;

    const __half* asrc = g_atth + (size_t)(m0 + lrow) * 512 + seg * 8;
    const __half* bsrc = g_wo_h + (size_t)(n0 + lrow) * 512 + seg * 8;

    const uint32_t s0 = (uint32_t)__cvta_generic_to_shared(smem);
    const uint32_t adst = s0 + lrow * 128 + ((seg ^ (lrow & 7)) << 4);
    const uint32_t bdst = adst + ATILEB;

    const uint32_t arow_off = (uint32_t)((wm * 64 + (lane & 15)) * 128);
    const uint32_t brow_off = (uint32_t)((wn * 64 + (lane & 15)) * 128);
    uint32_t swk[4];
    #pragma unroll
    for (int kk = 0; kk < 4; kk++)
        swk[kk] = (uint32_t)((((2 * kk + (lane >> 4)) ^ (lane & 7)) << 4));

    float acc[4][8][4];
    #pragma unroll
    for (int i = 0; i < 4; i++)
        #pragma unroll
        for (int j = 0; j < 8; j++)
            #pragma unroll
            for (int q = 0; q < 4; q++) acc[i][j][q] = 0.f;

    auto load = [&](int it, int buf) {
        const int k0 = it * 64;
        const uint32_t off = buf * STAGEB;
        #pragma unroll
        for (int i = 0; i < 8; i++)
            cp16(adst + off + i * 16 * 128, asrc + k0 + (size_t)i * 16 * 512);
        #pragma unroll
        for (int i = 0; i < 8; i++)
            cp16(bdst + off + i * 16 * 128, bsrc + k0 + (size_t)i * 16 * 512);
        cp_commit();
    };

    load(0, 0);

    #pragma unroll 1
    for (int it = 0; it < 8; ++it) {
        cp_waitg<0>();
        __syncthreads();
        if (it < 7) load(it + 1, (it + 1) & 1);
        const uint32_t st = s0 + (it & 1) * STAGEB;
        compute_stage64h(st + arow_off, st + ATILEB + brow_off, swk, acc);
    }

    #pragma unroll
    for (int i = 0; i < 4; i++) {
        const int r0 = m0 + wm * 64 + i * 16 + (lane >> 2);
        #pragma unroll
        for (int j = 0; j < 8; j++) {
            const int col = n0 + wn * 64 + j * 8 + (lane & 3) * 2;
            const float b0 = bias[col], b1 = bias[col + 1];
            float2 o0 = make_float2(acc[i][j][0] + b0, acc[i][j][1] + b1);
            float2 o1 = make_float2(acc[i][j][2] + b0, acc[i][j][3] + b1);
            *reinterpret_cast<float2*>(&out[(size_t)r0 * 512 + col]) = o0;
            *reinterpret_cast<float2*>(&out[(size_t)(r0 + 8) * 512 + col]) = o1;
        }
    }
}

// =====================================================================
extern "C" void kernel_launch(void* const* d_in, const int* in_sizes, int n_in,
                              void* d_out, int out_size)
{
    const float* x   = (const float*)d_in[0];
    const float* wi  = (const float*)d_in[1];
    const float* bi  = (const float*)d_in[2];
    const float* wo  = (const float*)d_in[3];
    const float* bo  = (const float*)d_in[4];
    const float* rpe = (const float*)d_in[5];
    float* out = (float*)d_out;

    static bool attr_done = false;
    if (!attr_done) {
        cudaFuncSetAttribute(qkv_gemm_mma,
            cudaFuncAttributeMaxDynamicSharedMemorySize, GSMEMB);
        cudaFuncSetAttribute(out_gemm_mma,
            cudaFuncAttributeMaxDynamicSharedMemorySize, GSMEMB);
        cudaFuncSetAttribute(attn_mma,
            cudaFuncAttributeMaxDynamicSharedMemorySize, AT_SMEMB);
        attr_done = true;
    }

    const int mtiles = M_IMG / 128;   // 1024

    cvt_all<<<4096, 256>>>(x, wi, wo, bi, rpe);
    qkv_gemm_mma<<<dim3(1536 / 128, mtiles), 128, GSMEMB>>>(bi);
    attn_mma<<<dim3(NB, NHEADS), 64, AT_SMEMB>>>();
    out_gemm_mma<<<dim3(512 / 128, mtiles), 128, GSMEMB>>>(bo, out);
}